// round 2
// baseline (speedup 1.0000x reference)
#include <cuda_runtime.h>
#include <cstdint>

#define B_SZ   64
#define IN_F   8192
#define OUT_F  8192
#define NNZ    262144
#define K8     8

// ---------------- device scratch (no allocations allowed) ----------------
__device__ __align__(16) float g_t[(size_t)IN_F * B_SZ];  // 2 MB, [col][batch]
__device__ int g_count[OUT_F];    // zero-init at load; re-zeroed by spmm each call
__device__ int g_start[OUT_F];
__device__ int g_cursor[OUT_F];
__device__ int g_perm[NNZ];

// ---------------- K1: fused tanh table + row histogram ----------------
// precondition: g_count == 0 (static init on first call; spmm re-zeroes after)
__global__ void tanh_hist_kernel(const float* __restrict__ x,
                                 const int*   __restrict__ rows) {
    int idx = blockIdx.x * blockDim.x + threadIdx.x;   // 0 .. B*IN_F-1
    if (idx < NNZ) atomicAdd(&g_count[rows[idx]], 1);
    if (idx >= B_SZ * IN_F) return;
    int b = idx >> 13;          // / IN_F
    int c = idx & (IN_F - 1);
    const float CLIP = 1.0f - 1e-7f;
    float t = tanhf(x[idx]);
    t = fminf(fmaxf(t, -CLIP), CLIP);
    g_t[(size_t)c * B_SZ + b] = t;
}

// ---------------- K2: exclusive scan over 8192 counters (1 CTA, shfl) ----------------
__global__ void scan_kernel() {
    int t    = threadIdx.x;        // 0..1023
    int lane = t & 31, wid = t >> 5;
    int base = t * 8;
    int v[8];
    int run = 0;
#pragma unroll
    for (int i = 0; i < 8; i++) {
        v[i] = run;
        run += g_count[base + i];
    }
    // warp inclusive scan of per-thread totals
    int x = run;
#pragma unroll
    for (int off = 1; off < 32; off <<= 1) {
        int y = __shfl_up_sync(0xFFFFFFFFu, x, off);
        if (lane >= off) x += y;
    }
    __shared__ int wsum[32];
    if (lane == 31) wsum[wid] = x;
    __syncthreads();
    if (wid == 0) {
        int y = wsum[lane];
#pragma unroll
        for (int off = 1; off < 32; off <<= 1) {
            int z = __shfl_up_sync(0xFFFFFFFFu, y, off);
            if (lane >= off) y += z;
        }
        wsum[lane] = y;
    }
    __syncthreads();
    int warp_excl = (wid > 0) ? wsum[wid - 1] : 0;
    int thr_excl  = warp_excl + (x - run);   // exclusive offset for this thread
#pragma unroll
    for (int i = 0; i < 8; i++) {
        int st = thr_excl + v[i];
        g_start[base + i]  = st;
        g_cursor[base + i] = st;
    }
}

// ---------------- K3: scatter edge ids into row buckets ----------------
__global__ void scatter_kernel(const int* __restrict__ rows) {
    int i = blockIdx.x * blockDim.x + threadIdx.x;
    if (i < NNZ) {
        int p = atomicAdd(&g_cursor[rows[i]], 1);
        g_perm[p] = i;
    }
}

// ---------------- K4: main SpMM — one warp per row, recurrence in registers ----
__device__ __forceinline__ float cheb_dot(float t, float4 w0, float4 w1) {
    float acc = fmaf(w0.y, t, w0.x);
    float T0 = 1.0f, T1 = t;
    float t2 = t + t;
    float Tn;
    Tn = fmaf(t2, T1, -T0); acc = fmaf(w0.z, Tn, acc); T0 = T1; T1 = Tn;
    Tn = fmaf(t2, T1, -T0); acc = fmaf(w0.w, Tn, acc); T0 = T1; T1 = Tn;
    Tn = fmaf(t2, T1, -T0); acc = fmaf(w1.x, Tn, acc); T0 = T1; T1 = Tn;
    Tn = fmaf(t2, T1, -T0); acc = fmaf(w1.y, Tn, acc); T0 = T1; T1 = Tn;
    Tn = fmaf(t2, T1, -T0); acc = fmaf(w1.z, Tn, acc); T0 = T1; T1 = Tn;
    Tn = fmaf(t2, T1, -T0); acc = fmaf(w1.w, Tn, acc);
    return acc;
}

// 256 threads = 8 warps = 8 consecutive rows per block. Lane owns batches (2l, 2l+1).
__global__ void __launch_bounds__(256) spmm_kernel(const float* __restrict__ weight,
                                                   const int*   __restrict__ cols,
                                                   float* __restrict__ out) {
    __shared__ float s[8][65];     // padded transpose buffer
    int wid  = threadIdx.x >> 5;
    int lane = threadIdx.x & 31;
    int r0   = blockIdx.x * 8;
    int r    = r0 + wid;

    int start = g_start[r];
    int n     = g_count[r];

    float acc0 = 0.0f, acc1 = 0.0f;

    int e = 0, c = 0;
    if (n > 0) { e = g_perm[start]; c = cols[e]; }
    for (int j = 0; j < n; j++) {
        int e_cur = e, c_cur = c;
        if (j + 1 < n) {                      // prefetch next edge's indices
            e = g_perm[start + j + 1];
            c = cols[e];
        }
        const float4* wp = reinterpret_cast<const float4*>(weight + (size_t)e_cur * K8);
        float4 w0 = __ldg(wp);
        float4 w1 = __ldg(wp + 1);
        float2 tt = *reinterpret_cast<const float2*>(&g_t[(size_t)c_cur * B_SZ + 2 * lane]);
        acc0 += cheb_dot(tt.x, w0, w1);
        acc1 += cheb_dot(tt.y, w0, w1);
    }

    if (lane == 0) g_count[r] = 0;            // reset histogram for next call

    s[wid][2 * lane]     = acc0;
    s[wid][2 * lane + 1] = acc1;
    __syncthreads();

    // 64 threads each write one batch's 8 consecutive outputs (2x float4 = 32B sector)
    if (threadIdx.x < 64) {
        int b = threadIdx.x;
        float4 v0 = make_float4(s[0][b], s[1][b], s[2][b], s[3][b]);
        float4 v1 = make_float4(s[4][b], s[5][b], s[6][b], s[7][b]);
        float4* op = reinterpret_cast<float4*>(out + (size_t)b * OUT_F + r0);
        op[0] = v0;
        op[1] = v1;
    }
}

// ---------------- launcher ----------------
extern "C" void kernel_launch(void* const* d_in, const int* in_sizes, int n_in,
                              void* d_out, int out_size) {
    const float* x      = (const float*)d_in[0];   // [64, 8192]
    const float* weight = (const float*)d_in[1];   // [262144, 8]
    const int*   rows   = (const int*)  d_in[2];   // [262144]
    const int*   cols   = (const int*)  d_in[3];   // [262144]
    float*       out    = (float*)d_out;           // [64, 8192]

    tanh_hist_kernel<<<(B_SZ * IN_F + 255) / 256, 256>>>(x, rows);
    scan_kernel     <<<1, 1024>>>();
    scatter_kernel  <<<(NNZ + 255) / 256, 256>>>(rows);
    spmm_kernel     <<<OUT_F / 8, 256>>>(weight, cols, out);
}

// round 3
// speedup vs baseline: 1.2797x; 1.2797x over previous
#include <cuda_runtime.h>
#include <cstdint>

#define B_SZ   64
#define IN_F   8192
#define OUT_F  8192
#define NNZ    262144
#define K8     8

// ---------------- device scratch (no allocations allowed) ----------------
__device__ __align__(16) float  g_t[(size_t)IN_F * B_SZ];   // 2 MB, [col][batch]
__device__ int    g_count[OUT_F];     // zero-init at load; re-zeroed by spmm each call
__device__ int    g_start[OUT_F];
__device__ int    g_cursor[OUT_F];
__device__ int    g_c[NNZ];                                  // cols in CSR order
__device__ __align__(16) float4 g_w[(size_t)NNZ * 2];        // weights in CSR order (8MB)

// ---------------- K1: fused tanh table + row histogram ----------------
__global__ void tanh_hist_kernel(const float* __restrict__ x,
                                 const int*   __restrict__ rows) {
    int idx = blockIdx.x * blockDim.x + threadIdx.x;   // 0 .. B*IN_F-1
    if (idx < NNZ) atomicAdd(&g_count[rows[idx]], 1);
    if (idx >= B_SZ * IN_F) return;
    int b = idx >> 13;          // / IN_F
    int c = idx & (IN_F - 1);
    const float CLIP = 1.0f - 1e-7f;
    float t = tanhf(x[idx]);
    t = fminf(fmaxf(t, -CLIP), CLIP);
    g_t[(size_t)c * B_SZ + b] = t;
}

// ---------------- K2: exclusive scan over 8192 counters (1 CTA, shfl) ------
__global__ void scan_kernel() {
    int t    = threadIdx.x;        // 0..1023
    int lane = t & 31, wid = t >> 5;
    int base = t * 8;
    int v[8];
    int run = 0;
#pragma unroll
    for (int i = 0; i < 8; i++) {
        v[i] = run;
        run += g_count[base + i];
    }
    int x = run;
#pragma unroll
    for (int off = 1; off < 32; off <<= 1) {
        int y = __shfl_up_sync(0xFFFFFFFFu, x, off);
        if (lane >= off) x += y;
    }
    __shared__ int wsum[32];
    if (lane == 31) wsum[wid] = x;
    __syncthreads();
    if (wid == 0) {
        int y = wsum[lane];
#pragma unroll
        for (int off = 1; off < 32; off <<= 1) {
            int z = __shfl_up_sync(0xFFFFFFFFu, y, off);
            if (lane >= off) y += z;
        }
        wsum[lane] = y;
    }
    __syncthreads();
    int warp_excl = (wid > 0) ? wsum[wid - 1] : 0;
    int thr_excl  = warp_excl + (x - run);
#pragma unroll
    for (int i = 0; i < 8; i++) {
        int st = thr_excl + v[i];
        g_start[base + i]  = st;
        g_cursor[base + i] = st;
    }
}

// ---------------- K3: scatter cols + weights into CSR order ----------------
__global__ void scatter_kernel(const int*   __restrict__ rows,
                               const int*   __restrict__ cols,
                               const float* __restrict__ weight) {
    int i = blockIdx.x * blockDim.x + threadIdx.x;
    if (i >= NNZ) return;
    const float4* wp = reinterpret_cast<const float4*>(weight + (size_t)i * K8);
    float4 w0 = wp[0];
    float4 w1 = wp[1];
    int c = cols[i];
    int p = atomicAdd(&g_cursor[rows[i]], 1);
    g_c[p] = c;
    g_w[2 * (size_t)p]     = w0;
    g_w[2 * (size_t)p + 1] = w1;
}

// ---------------- K4: main SpMM — pipelined, sequential c/w streams --------
__device__ __forceinline__ float cheb_dot(float t, float4 w0, float4 w1) {
    float acc = fmaf(w0.y, t, w0.x);
    float T0 = 1.0f, T1 = t;
    float t2 = t + t;
    float Tn;
    Tn = fmaf(t2, T1, -T0); acc = fmaf(w0.z, Tn, acc); T0 = T1; T1 = Tn;
    Tn = fmaf(t2, T1, -T0); acc = fmaf(w0.w, Tn, acc); T0 = T1; T1 = Tn;
    Tn = fmaf(t2, T1, -T0); acc = fmaf(w1.x, Tn, acc); T0 = T1; T1 = Tn;
    Tn = fmaf(t2, T1, -T0); acc = fmaf(w1.y, Tn, acc); T0 = T1; T1 = Tn;
    Tn = fmaf(t2, T1, -T0); acc = fmaf(w1.z, Tn, acc); T0 = T1; T1 = Tn;
    Tn = fmaf(t2, T1, -T0); acc = fmaf(w1.w, Tn, acc);
    return acc;
}

// 256 threads = 8 warps = 8 consecutive rows per block. Lane owns batches (2l, 2l+1).
__global__ void __launch_bounds__(256) spmm_kernel(float* __restrict__ out) {
    __shared__ float s[8][65];
    int wid  = threadIdx.x >> 5;
    int lane = threadIdx.x & 31;
    int lane2 = lane * 2;
    int r0   = blockIdx.x * 8;
    int r    = r0 + wid;

    int start = g_start[r];
    int n     = g_count[r];

    const int*    cp = g_c + start;
    const float4* wp = g_w + (size_t)start * 2;

    float acc0 = 0.0f, acc1 = 0.0f;

    if (n > 0) {
        float2 tb[2][4];
        // prologue: issue chunk 0's t loads
#pragma unroll
        for (int i = 0; i < 4; i++) {
            int j  = (i < n) ? i : (n - 1);
            int cc = cp[j];
            tb[0][i] = *reinterpret_cast<const float2*>(g_t + (size_t)cc * B_SZ + lane2);
        }
        int cur = 0;
        for (int base = 0; base < n; base += 4) {
            int nxt = cur ^ 1;
            // issue next chunk's t loads (c from sequential array, fast)
            if (base + 4 < n) {
#pragma unroll
                for (int i = 0; i < 4; i++) {
                    int j  = base + 4 + i;
                    if (j >= n) j = n - 1;
                    int cc = cp[j];
                    tb[nxt][i] = *reinterpret_cast<const float2*>(g_t + (size_t)cc * B_SZ + lane2);
                }
            }
            // compute current chunk (sequential w loads, L2-hot)
#pragma unroll
            for (int i = 0; i < 4; i++) {
                int j = base + i;
                float4 w0, w1;
                if (j < n) {
                    w0 = __ldg(wp + 2 * j);
                    w1 = __ldg(wp + 2 * j + 1);
                } else {
                    w0 = make_float4(0.f, 0.f, 0.f, 0.f);
                    w1 = w0;
                }
                acc0 += cheb_dot(tb[cur][i].x, w0, w1);
                acc1 += cheb_dot(tb[cur][i].y, w0, w1);
            }
            cur = nxt;
        }
    }

    if (lane == 0) g_count[r] = 0;            // reset histogram for next call

    s[wid][lane2]     = acc0;
    s[wid][lane2 + 1] = acc1;
    __syncthreads();

    // 64 threads each write one batch's 8 consecutive outputs (2x float4)
    if (threadIdx.x < 64) {
        int b = threadIdx.x;
        float4 v0 = make_float4(s[0][b], s[1][b], s[2][b], s[3][b]);
        float4 v1 = make_float4(s[4][b], s[5][b], s[6][b], s[7][b]);
        float4* op = reinterpret_cast<float4*>(out + (size_t)b * OUT_F + r0);
        op[0] = v0;
        op[1] = v1;
    }
}

// ---------------- launcher ----------------
extern "C" void kernel_launch(void* const* d_in, const int* in_sizes, int n_in,
                              void* d_out, int out_size) {
    const float* x      = (const float*)d_in[0];   // [64, 8192]
    const float* weight = (const float*)d_in[1];   // [262144, 8]
    const int*   rows   = (const int*)  d_in[2];   // [262144]
    const int*   cols   = (const int*)  d_in[3];   // [262144]
    float*       out    = (float*)d_out;           // [64, 8192]

    tanh_hist_kernel<<<(B_SZ * IN_F + 255) / 256, 256>>>(x, rows);
    scan_kernel     <<<1, 1024>>>();
    scatter_kernel  <<<(NNZ + 255) / 256, 256>>>(rows, cols, weight);
    spmm_kernel     <<<OUT_F / 8, 256>>>(out);
}

// round 5
// speedup vs baseline: 1.2834x; 1.0029x over previous
#include <cuda_runtime.h>
#include <cstdint>

#define B_SZ   64
#define IN_F   8192
#define OUT_F  8192
#define NNZ    262144
#define K8     8

// ---------------- device scratch (no allocations allowed) ----------------
__device__ __align__(16) float  g_t[(size_t)IN_F * B_SZ];   // 2 MB, [col][batch]
__device__ int    g_count[OUT_F];     // zero-init at load; re-zeroed by spmm each call
__device__ int    g_start[OUT_F];
__device__ int    g_cursor[OUT_F];
__device__ int    g_c[NNZ];                                  // cols in CSR order
__device__ __align__(16) float g_p[(size_t)NNZ * K8];        // monomial coeffs, CSR order (8MB)

// ---------------- K1: fused tanh table + row histogram ----------------
__global__ void tanh_hist_kernel(const float* __restrict__ x,
                                 const int*   __restrict__ rows) {
    int idx = blockIdx.x * blockDim.x + threadIdx.x;   // 0 .. B*IN_F-1
    if (idx < NNZ) atomicAdd(&g_count[rows[idx]], 1);
    if (idx >= B_SZ * IN_F) return;
    int b = idx >> 13;          // / IN_F
    int c = idx & (IN_F - 1);
    const float CLIP = 1.0f - 1e-7f;
    float t = tanhf(x[idx]);
    t = fminf(fmaxf(t, -CLIP), CLIP);
    g_t[(size_t)c * B_SZ + b] = t;
}

// ---------------- K2: exclusive scan over 8192 counters (1 CTA, shfl) ------
__global__ void scan_kernel() {
    int t    = threadIdx.x;        // 0..1023
    int lane = t & 31, wid = t >> 5;
    int base = t * 8;
    int v[8];
    int run = 0;
#pragma unroll
    for (int i = 0; i < 8; i++) {
        v[i] = run;
        run += g_count[base + i];
    }
    int x = run;
#pragma unroll
    for (int off = 1; off < 32; off <<= 1) {
        int y = __shfl_up_sync(0xFFFFFFFFu, x, off);
        if (lane >= off) x += y;
    }
    __shared__ int wsum[32];
    if (lane == 31) wsum[wid] = x;
    __syncthreads();
    if (wid == 0) {
        int y = wsum[lane];
#pragma unroll
        for (int off = 1; off < 32; off <<= 1) {
            int z = __shfl_up_sync(0xFFFFFFFFu, y, off);
            if (lane >= off) y += z;
        }
        wsum[lane] = y;
    }
    __syncthreads();
    int warp_excl = (wid > 0) ? wsum[wid - 1] : 0;
    int thr_excl  = warp_excl + (x - run);
#pragma unroll
    for (int i = 0; i < 8; i++) {
        int st = thr_excl + v[i];
        g_start[base + i]  = st;
        g_cursor[base + i] = st;
    }
}

// -------- K3: scatter cols + Chebyshev->monomial coeffs into CSR order -----
// p = M*w so that sum_k w_k T_k(t) == sum_k p_k t^k  (Horner-ready)
__global__ void scatter_kernel(const int*   __restrict__ rows,
                               const int*   __restrict__ cols,
                               const float* __restrict__ weight) {
    int i = blockIdx.x * blockDim.x + threadIdx.x;
    if (i >= NNZ) return;
    const float4* wp = reinterpret_cast<const float4*>(weight + (size_t)i * K8);
    float4 a = wp[0];   // w0..w3
    float4 b = wp[1];   // w4..w7
    float4 p0, p1;
    p0.x = a.x - a.z + b.x - b.z;                       // w0 -  w2 +  w4 -  w6
    p0.y = a.y - 3.f*a.w + 5.f*b.y - 7.f*b.w;           // w1 - 3w3 + 5w5 - 7w7
    p0.z = 2.f*a.z - 8.f*b.x + 18.f*b.z;                // 2w2 - 8w4 + 18w6
    p0.w = 4.f*a.w - 20.f*b.y + 56.f*b.w;               // 4w3 - 20w5 + 56w7
    p1.x = 8.f*b.x - 48.f*b.z;                          // 8w4 - 48w6
    p1.y = 16.f*b.y - 112.f*b.w;                        // 16w5 - 112w7
    p1.z = 32.f*b.z;                                    // 32w6
    p1.w = 64.f*b.w;                                    // 64w7
    int c = cols[i];
    int p = atomicAdd(&g_cursor[rows[i]], 1);
    g_c[p] = c;
    float4* dst = reinterpret_cast<float4*>(g_p + (size_t)p * K8);
    dst[0] = p0;
    dst[1] = p1;
}

// ---------------- K4: main SpMM — fully prefetched, Horner ----------------
// 256 threads = 8 warps = 8 consecutive rows per block. Lane owns batches (2l, 2l+1).
// Per 4-edge chunk: t prefetched as 4x float2 regs; the chunk's 32 weight
// floats prefetched as ONE coalesced float per lane, extracted via shfl.
__global__ void __launch_bounds__(256) spmm_kernel(float* __restrict__ out) {
    __shared__ float s[8][65];
    int wid   = threadIdx.x >> 5;
    int lane  = threadIdx.x & 31;
    int lane2 = lane * 2;
    int r0    = blockIdx.x * 8;
    int r     = r0 + wid;

    int start = g_start[r];
    int n     = g_count[r];

    const int*   cp = g_c + start;
    const float* pp = g_p + (size_t)start * K8;

    float acc0 = 0.0f, acc1 = 0.0f;

    float2 tA[4], tB[4];
    float  wA = 0.f, wB = 0.f;

    // prefetch chunk at edge-offset `base` into (tb, wv); indices clamped to valid range
#define PREFETCH(tb, wv, base)                                                   \
    do {                                                                         \
        int _b = (base);                                                         \
        if (_b < n) {                                                            \
            _Pragma("unroll")                                                    \
            for (int _i = 0; _i < 4; _i++) {                                     \
                int _j = _b + _i; if (_j >= n) _j = n - 1;                       \
                int _cc = __ldg(cp + _j);                                        \
                (tb)[_i] = *reinterpret_cast<const float2*>(                     \
                    g_t + (size_t)_cc * B_SZ + lane2);                           \
            }                                                                    \
            size_t _w = (size_t)_b * K8 + lane;                                  \
            size_t _wmax = (size_t)n * K8 - 1;                                   \
            (wv) = __ldg(pp + (_w <= _wmax ? _w : _wmax));                       \
        }                                                                        \
    } while (0)

#define COMPUTE(tb, wv, base)                                                    \
    do {                                                                         \
        int _b = (base);                                                         \
        _Pragma("unroll")                                                        \
        for (int _i = 0; _i < 4; _i++) {                                         \
            if (_b + _i < n) {                                                   \
                float q0 = __shfl_sync(0xFFFFFFFFu, (wv), _i * 8 + 0);           \
                float q1 = __shfl_sync(0xFFFFFFFFu, (wv), _i * 8 + 1);           \
                float q2 = __shfl_sync(0xFFFFFFFFu, (wv), _i * 8 + 2);           \
                float q3 = __shfl_sync(0xFFFFFFFFu, (wv), _i * 8 + 3);           \
                float q4 = __shfl_sync(0xFFFFFFFFu, (wv), _i * 8 + 4);           \
                float q5 = __shfl_sync(0xFFFFFFFFu, (wv), _i * 8 + 5);           \
                float q6 = __shfl_sync(0xFFFFFFFFu, (wv), _i * 8 + 6);           \
                float q7 = __shfl_sync(0xFFFFFFFFu, (wv), _i * 8 + 7);           \
                float tx = (tb)[_i].x, ty = (tb)[_i].y;                          \
                float h0 = q7, h1 = q7;                                          \
                h0 = fmaf(h0, tx, q6); h1 = fmaf(h1, ty, q6);                    \
                h0 = fmaf(h0, tx, q5); h1 = fmaf(h1, ty, q5);                    \
                h0 = fmaf(h0, tx, q4); h1 = fmaf(h1, ty, q4);                    \
                h0 = fmaf(h0, tx, q3); h1 = fmaf(h1, ty, q3);                    \
                h0 = fmaf(h0, tx, q2); h1 = fmaf(h1, ty, q2);                    \
                h0 = fmaf(h0, tx, q1); h1 = fmaf(h1, ty, q1);                    \
                h0 = fmaf(h0, tx, q0); h1 = fmaf(h1, ty, q0);                    \
                acc0 += h0; acc1 += h1;                                          \
            }                                                                    \
        }                                                                        \
    } while (0)

    if (n > 0) {
        PREFETCH(tA, wA, 0);
        for (int base = 0; base < n; base += 8) {
            PREFETCH(tB, wB, base + 4);
            COMPUTE(tA, wA, base);
            PREFETCH(tA, wA, base + 8);
            COMPUTE(tB, wB, base + 4);
        }
    }
#undef PREFETCH
#undef COMPUTE

    if (lane == 0) g_count[r] = 0;            // reset histogram for next call

    s[wid][lane2]     = acc0;
    s[wid][lane2 + 1] = acc1;
    __syncthreads();

    // 64 threads each write one batch's 8 consecutive outputs (2x float4)
    if (threadIdx.x < 64) {
        int b = threadIdx.x;
        float4 v0 = make_float4(s[0][b], s[1][b], s[2][b], s[3][b]);
        float4 v1 = make_float4(s[4][b], s[5][b], s[6][b], s[7][b]);
        float4* op = reinterpret_cast<float4*>(out + (size_t)b * OUT_F + r0);
        op[0] = v0;
        op[1] = v1;
    }
}

// ---------------- launcher ----------------
extern "C" void kernel_launch(void* const* d_in, const int* in_sizes, int n_in,
                              void* d_out, int out_size) {
    const float* x      = (const float*)d_in[0];   // [64, 8192]
    const float* weight = (const float*)d_in[1];   // [262144, 8]
    const int*   rows   = (const int*)  d_in[2];   // [262144]
    const int*   cols   = (const int*)  d_in[3];   // [262144]
    float*       out    = (float*)d_out;           // [64, 8192]

    tanh_hist_kernel<<<(B_SZ * IN_F + 255) / 256, 256>>>(x, rows);
    scan_kernel     <<<1, 1024>>>();
    scatter_kernel  <<<(NNZ + 255) / 256, 256>>>(rows, cols, weight);
    spmm_kernel     <<<OUT_F / 8, 256>>>(out);
}